// round 16
// baseline (speedup 1.0000x reference)
#include <cuda_runtime.h>
#include <math.h>
#include <stddef.h>

#define BSZ 256
#define SSZ 128
#define ESZ 256
#define HSZ 512
#define GSZ 2048   // 4*H (interleaved gate cols)
#define NC  2560   // decoder: 2048 interleaved gates + 512 (q)
#define NB2 4096

// ---------- device scratch ----------
__device__ float  g_WencG[HSZ * GSZ];
__device__ float  g_W1T[HSZ * HSZ];
__device__ float  g_WdecT[HSZ * NC];
__device__ float  g_WihT[ESZ * NB2];
__device__ float  g_emb[(size_t)BSZ * SSZ * ESZ];
__device__ float  g_xg_enc[(size_t)BSZ * SSZ * GSZ];
__device__ float  g_xg_dec[(size_t)BSZ * SSZ * GSZ];
__device__ float  g_proj[(size_t)BSZ * SSZ * HSZ];
__device__ float  g_hall[(size_t)(SSZ + 1) * BSZ * HSZ];
__device__ float  g_hdec[BSZ * HSZ];
__device__ float  g_C[BSZ * GSZ];
__device__ float  g_c[BSZ * HSZ];
__device__ float  g_q[BSZ * HSZ];
__device__ float  g_xg0[GSZ];
__device__ float  g_us[BSZ * SSZ];
__device__ int    g_mask[BSZ * SSZ];

// ---------- frozen numerics ----------
__device__ __forceinline__ float xtanh(float x) { return tanhf(x); }
__device__ __forceinline__ float sigf(float x) {
    return __fdiv_rn(1.0f, __fadd_rn(1.0f, expf(-x)));
}
__device__ __forceinline__ int deint(int n) { return (n & 3) * HSZ + (n >> 2); }

// ---------- packed helpers kept for xg/proj (bit-identical per lane) ----------
__device__ __forceinline__ unsigned long long pack2(float lo, float hi) {
    unsigned long long r;
    asm("mov.b64 %0, {%1, %2};" : "=l"(r) : "f"(lo), "f"(hi));
    return r;
}
__device__ __forceinline__ void unpack2(unsigned long long v, float& lo, float& hi) {
    asm("mov.b64 {%0, %1}, %2;" : "=f"(lo), "=f"(hi) : "l"(v));
}
__device__ __forceinline__ void ffma2(unsigned long long& d, unsigned long long a, unsigned long long b) {
    asm("fma.rn.f32x2 %0, %1, %2, %3;" : "=l"(d) : "l"(a), "l"(b), "l"(d));
}

// ---------- state init ----------
__global__ void init_kernel(const float* __restrict__ h0, const float* __restrict__ c0,
                            const float* __restrict__ inputs) {
    int i = blockIdx.x * blockDim.x + threadIdx.x;
    if (i < BSZ * HSZ) {
        g_hall[i] = h0[i & (HSZ - 1)];
        g_c[i]    = c0[i & (HSZ - 1)];
    }
    if (i < BSZ * SSZ) g_mask[i] = (inputs[(size_t)i * 2] > 0.0f) ? 1 : 0;
}

// ---------- weight transposes ----------
__global__ void transpose_kernel(const float* __restrict__ encWhh, const float* __restrict__ W1,
                                 const float* __restrict__ decWhh, const float* __restrict__ W2) {
    int i = blockIdx.x * blockDim.x + threadIdx.x;
    if (i >= HSZ * NC) return;
    int k = i / NC, n = i % NC;
    if (n < GSZ) {
        int orig = deint(n);
        g_WencG[k * GSZ + n] = encWhh[orig * HSZ + k];
        g_WdecT[i] = decWhh[orig * HSZ + k];
    } else {
        int n2 = n - GSZ;
        g_W1T[k * HSZ + n2] = W1[n2 * HSZ + k];
        g_WdecT[i] = W2[n2 * HSZ + k];
    }
}
__global__ void wiht_kernel(const float* __restrict__ encWih, const float* __restrict__ decWih) {
    int i = blockIdx.x * blockDim.x + threadIdx.x;
    if (i >= ESZ * NB2) return;
    int k = i / NB2, n = i % NB2;
    float v;
    if (n < GSZ) v = encWih[deint(n) * ESZ + k];
    else         v = decWih[deint(n - GSZ) * ESZ + k];
    g_WihT[i] = v;
}

// ---------- emb ----------
__global__ void emb_kernel(const float* __restrict__ inputs, const float* __restrict__ embW,
                           const float* __restrict__ embB) {
    int i = blockIdx.x * blockDim.x + threadIdx.x;
    if (i >= BSZ * SSZ * ESZ) return;
    int e = i % ESZ, bs = i / ESZ;
    float in0 = inputs[(size_t)bs * 2], in1 = inputs[(size_t)bs * 2 + 1];
    float mm = fmaf(in1, embW[2 * e + 1], __fmul_rn(in0, embW[2 * e]));
    g_emb[i] = __fadd_rn(mm, embB[e]);
}

// ---------- decoder step-0 input gates ----------
__global__ void xg0_kernel(const float* __restrict__ decWih, const float* __restrict__ dbih,
                           const float* __restrict__ dbhh, const float* __restrict__ dec0) {
    int n = blockIdx.x * blockDim.x + threadIdx.x;
    if (n >= GSZ) return;
    int orig = deint(n);
    float acc = 0.f;
    for (int e = 0; e < ESZ; e++) acc = fmaf(dec0[e], decWih[orig * ESZ + e], acc);
    g_xg0[n] = __fadd_rn(__fadd_rn(acc, dbih[orig]), dbhh[orig]);
}

// ---------- xg precompute GEMM (unchanged, one-shot) ----------
__global__ void __launch_bounds__(256) xg_gemm(const float* __restrict__ ebih, const float* __restrict__ ebhh,
                                               const float* __restrict__ dbih, const float* __restrict__ dbhh) {
    __shared__ __align__(16) float As[16][64 + 4];
    __shared__ __align__(16) float Bs[16][64];
    const int tid = threadIdx.x;
    const int row0 = blockIdx.y * 64;
    const int n0 = blockIdx.x * 64;
    const int lr = tid >> 2, lk = (tid & 3) << 2;
    const int bk = tid >> 4, bn = (tid & 15) << 2;
    const int tm = tid & 15, tn = tid >> 4;

    unsigned long long acc2[4][2];
#pragma unroll
    for (int i = 0; i < 4; i++)
#pragma unroll
        for (int j = 0; j < 2; j++) acc2[i][j] = pack2(0.f, 0.f);

    {
        float4 av = *reinterpret_cast<const float4*>(g_emb + (size_t)(row0 + lr) * ESZ + lk);
        As[lk + 0][lr] = av.x; As[lk + 1][lr] = av.y;
        As[lk + 2][lr] = av.z; As[lk + 3][lr] = av.w;
        *reinterpret_cast<float4*>(&Bs[bk][bn]) =
            *reinterpret_cast<const float4*>(g_WihT + (size_t)bk * NB2 + n0 + bn);
    }
    __syncthreads();

    const int NKC = ESZ / 16;
    for (int kc = 0; kc < NKC; kc++) {
        float4 av; float4 bv;
        if (kc + 1 < NKC) {
            int k0 = (kc + 1) * 16;
            av = *reinterpret_cast<const float4*>(g_emb + (size_t)(row0 + lr) * ESZ + k0 + lk);
            bv = *reinterpret_cast<const float4*>(g_WihT + (size_t)(k0 + bk) * NB2 + n0 + bn);
        }
#pragma unroll
        for (int k = 0; k < 16; k++) {
            float4 a4 = *reinterpret_cast<const float4*>(&As[k][tm * 4]);
            float4 b4 = *reinterpret_cast<const float4*>(&Bs[k][tn * 4]);
            float ar[4] = {a4.x, a4.y, a4.z, a4.w};
            unsigned long long bp0 = pack2(b4.x, b4.y);
            unsigned long long bp1 = pack2(b4.z, b4.w);
#pragma unroll
            for (int i = 0; i < 4; i++) {
                unsigned long long ap = pack2(ar[i], ar[i]);
                ffma2(acc2[i][0], ap, bp0);
                ffma2(acc2[i][1], ap, bp1);
            }
        }
        __syncthreads();
        if (kc + 1 < NKC) {
            As[lk + 0][lr] = av.x; As[lk + 1][lr] = av.y;
            As[lk + 2][lr] = av.z; As[lk + 3][lr] = av.w;
            *reinterpret_cast<float4*>(&Bs[bk][bn]) = bv;
            __syncthreads();
        }
    }

#pragma unroll
    for (int i = 0; i < 4; i++) {
        size_t row = row0 + tm * 4 + i;
        float a0, a1, a2, a3;
        unpack2(acc2[i][0], a0, a1);
        unpack2(acc2[i][1], a2, a3);
        float accv[4] = {a0, a1, a2, a3};
#pragma unroll
        for (int j = 0; j < 4; j++) {
            int n = n0 + tn * 4 + j;
            if (n < GSZ) {
                int orig = deint(n);
                g_xg_enc[row * GSZ + n] = __fadd_rn(__fadd_rn(accv[j], ebih[orig]), ebhh[orig]);
            } else {
                int nd = n - GSZ;
                int orig = deint(nd);
                g_xg_dec[row * GSZ + nd] = __fadd_rn(__fadd_rn(accv[j], dbih[orig]), dbhh[orig]);
            }
        }
    }
}

// ---------- encoder step GEMM [256,2048], 512 threads, tile 64x64, 2x4/thread ----------
__global__ void __launch_bounds__(512) gemm_enc(const float* __restrict__ A,
                                                int do_cell,
                                                const float* __restrict__ xg,
                                                float* __restrict__ h_out) {
    __shared__ __align__(16) float As[16][64 + 4];
    __shared__ __align__(16) float Bs[16][64];
    __shared__ __align__(16) float Cs[64][64];

    const int tid = threadIdx.x;
    const int row0 = blockIdx.y * 64;
    const int n0 = blockIdx.x * 64;
    // loaders: tid<256 -> A float4 ; tid>=256 -> B float4
    const int lr = (tid & 255) >> 2;          // 0..63
    const int lk = (tid & 3) << 2;            // 0,4,8,12
    const int bk = (tid & 255) >> 4;          // 0..15
    const int bn = (tid & 15) << 2;           // 0..60
    // compute: 2 rows x 4 cols
    const int tm = tid & 31;                  // rows tm*2, tm*2+1
    const int tn = tid >> 5;                  // cols tn*4..tn*4+3

    float acc[2][4];
#pragma unroll
    for (int i = 0; i < 2; i++)
#pragma unroll
        for (int j = 0; j < 4; j++) acc[i][j] = 0.f;

    if (tid < 256) {
        float4 av = *reinterpret_cast<const float4*>(A + (size_t)(row0 + lr) * HSZ + lk);
        As[lk + 0][lr] = av.x; As[lk + 1][lr] = av.y;
        As[lk + 2][lr] = av.z; As[lk + 3][lr] = av.w;
    } else {
        *reinterpret_cast<float4*>(&Bs[bk][bn]) =
            *reinterpret_cast<const float4*>(g_WencG + (size_t)bk * GSZ + n0 + bn);
    }
    __syncthreads();

    const int NKC = HSZ / 16;  // 32
    for (int kc = 0; kc < NKC; kc++) {
        float4 pv;
        if (kc + 1 < NKC) {
            int k0 = (kc + 1) * 16;
            if (tid < 256)
                pv = *reinterpret_cast<const float4*>(A + (size_t)(row0 + lr) * HSZ + k0 + lk);
            else
                pv = *reinterpret_cast<const float4*>(g_WencG + (size_t)(k0 + bk) * GSZ + n0 + bn);
        }
#pragma unroll
        for (int k = 0; k < 16; k++) {
            float2 a2 = *reinterpret_cast<const float2*>(&As[k][tm * 2]);
            float4 b4 = *reinterpret_cast<const float4*>(&Bs[k][tn * 4]);
            float ar[2] = {a2.x, a2.y};
            float br[4] = {b4.x, b4.y, b4.z, b4.w};
#pragma unroll
            for (int i = 0; i < 2; i++)
#pragma unroll
                for (int j = 0; j < 4; j++) acc[i][j] = fmaf(ar[i], br[j], acc[i][j]);
        }
        __syncthreads();
        if (kc + 1 < NKC) {
            if (tid < 256) {
                As[lk + 0][lr] = pv.x; As[lk + 1][lr] = pv.y;
                As[lk + 2][lr] = pv.z; As[lk + 3][lr] = pv.w;
            } else {
                *reinterpret_cast<float4*>(&Bs[bk][bn]) = pv;
            }
            __syncthreads();
        }
    }

    if (!do_cell) {
#pragma unroll
        for (int i = 0; i < 2; i++) {
            int b = row0 + tm * 2 + i;
#pragma unroll
            for (int j = 0; j < 4; j++)
                g_C[(size_t)b * GSZ + n0 + tn * 4 + j] = acc[i][j];
        }
        return;
    }

#pragma unroll
    for (int i = 0; i < 2; i++)
#pragma unroll
        for (int j = 0; j < 4; j++)
            Cs[tm * 2 + i][tn * 4 + j] = acc[i][j];
    __syncthreads();

    // cell: 64 rows x 16 quads = 1024 items
    for (int it = tid; it < 64 * 16; it += 512) {
        int r = it >> 4, qi = it & 15;
        int b = row0 + r;
        int hh = (n0 >> 2) + qi;
        const float* xr = xg + (size_t)b * ((size_t)SSZ * GSZ) + n0 + 4 * qi;
        int c4 = 4 * qi;
        float gi = __fadd_rn(xr[0], Cs[r][c4 + 0]);
        float gf = __fadd_rn(xr[1], Cs[r][c4 + 1]);
        float gg = __fadd_rn(xr[2], Cs[r][c4 + 2]);
        float go = __fadd_rn(xr[3], Cs[r][c4 + 3]);
        float si = sigf(gi), sf = sigf(gf), so = sigf(go);
        float tg = xtanh(gg);
        int idx = b * HSZ + hh;
        float cn = __fadd_rn(__fmul_rn(sf, g_c[idx]), __fmul_rn(si, tg));
        g_c[idx] = cn;
        h_out[idx] = __fmul_rn(so, xtanh(cn));
    }
}

// ---------- standalone encoder cell (t=0) ----------
__global__ void __launch_bounds__(256) cell0_kernel(float* __restrict__ h_out,
                                                    const float* __restrict__ xg) {
    int idx = blockIdx.x * blockDim.x + threadIdx.x;
    int b = idx >> 9, hh = idx & (HSZ - 1);
    int n4 = 4 * hh;
    const float* Cb = g_C + (size_t)b * GSZ;
    const float* xr = xg + (size_t)b * ((size_t)SSZ * GSZ);
    float gi = __fadd_rn(xr[n4 + 0], Cb[n4 + 0]);
    float gf = __fadd_rn(xr[n4 + 1], Cb[n4 + 1]);
    float gg = __fadd_rn(xr[n4 + 2], Cb[n4 + 2]);
    float go = __fadd_rn(xr[n4 + 3], Cb[n4 + 3]);
    float si = sigf(gi), sf = sigf(gf), so = sigf(go);
    float tg = xtanh(gg);
    float cn = __fadd_rn(__fmul_rn(sf, g_c[idx]), __fmul_rn(si, tg));
    g_c[idx] = cn;
    h_out[idx] = __fmul_rn(so, xtanh(cn));
}

// ---------- big proj GEMM (unchanged, one-shot) ----------
__global__ void __launch_bounds__(256) proj_gemm(const float* __restrict__ b1) {
    __shared__ __align__(16) float As[16][64 + 4];
    __shared__ __align__(16) float Bs[16][64];
    const float* A = g_hall + (size_t)BSZ * HSZ;
    const int tid = threadIdx.x;
    const int row0 = blockIdx.y * 64;
    const int n0 = blockIdx.x * 64;
    const int lr = tid >> 2, lk = (tid & 3) << 2;
    const int bk = tid >> 4, bn = (tid & 15) << 2;
    const int tm = tid & 15, tn = tid >> 4;

    unsigned long long acc2[4][2];
#pragma unroll
    for (int i = 0; i < 4; i++)
#pragma unroll
        for (int j = 0; j < 2; j++) acc2[i][j] = pack2(0.f, 0.f);

    {
        float4 av = *reinterpret_cast<const float4*>(A + (size_t)(row0 + lr) * HSZ + lk);
        As[lk + 0][lr] = av.x; As[lk + 1][lr] = av.y;
        As[lk + 2][lr] = av.z; As[lk + 3][lr] = av.w;
        *reinterpret_cast<float4*>(&Bs[bk][bn]) =
            *reinterpret_cast<const float4*>(g_W1T + (size_t)bk * HSZ + n0 + bn);
    }
    __syncthreads();

    const int NKC = HSZ / 16;
    for (int kc = 0; kc < NKC; kc++) {
        float4 av; float4 bv;
        if (kc + 1 < NKC) {
            int k0 = (kc + 1) * 16;
            av = *reinterpret_cast<const float4*>(A + (size_t)(row0 + lr) * HSZ + k0 + lk);
            bv = *reinterpret_cast<const float4*>(g_W1T + (size_t)(k0 + bk) * HSZ + n0 + bn);
        }
#pragma unroll
        for (int k = 0; k < 16; k++) {
            float4 a4 = *reinterpret_cast<const float4*>(&As[k][tm * 4]);
            float4 b4 = *reinterpret_cast<const float4*>(&Bs[k][tn * 4]);
            float ar[4] = {a4.x, a4.y, a4.z, a4.w};
            unsigned long long bp0 = pack2(b4.x, b4.y);
            unsigned long long bp1 = pack2(b4.z, b4.w);
#pragma unroll
            for (int i = 0; i < 4; i++) {
                unsigned long long ap = pack2(ar[i], ar[i]);
                ffma2(acc2[i][0], ap, bp0);
                ffma2(acc2[i][1], ap, bp1);
            }
        }
        __syncthreads();
        if (kc + 1 < NKC) {
            As[lk + 0][lr] = av.x; As[lk + 1][lr] = av.y;
            As[lk + 2][lr] = av.z; As[lk + 3][lr] = av.w;
            *reinterpret_cast<float4*>(&Bs[bk][bn]) = bv;
            __syncthreads();
        }
    }

#pragma unroll
    for (int i = 0; i < 4; i++) {
        int r = row0 + tm * 4 + i;
        int s = r >> 8, b = r & (BSZ - 1);
        size_t orow = ((size_t)b * SSZ + s) * HSZ;
        float a0, a1, a2, a3;
        unpack2(acc2[i][0], a0, a1);
        unpack2(acc2[i][1], a2, a3);
        float accv[4] = {a0, a1, a2, a3};
#pragma unroll
        for (int j = 0; j < 4; j++) {
            int n = n0 + tn * 4 + j;
            g_proj[orow + n] = __fadd_rn(accv[j], b1[n]);
        }
    }
}

// ---------- decoder step GEMM [256,2560], 512 threads, tile 64x80, 2x5/thread ----------
#define BM 64
#define BN 80
__global__ void __launch_bounds__(512) gemm_dec(const float* __restrict__ A,
                                                float* __restrict__ dst2,
                                                const float* __restrict__ bias2,
                                                int do_cell,
                                                const float* __restrict__ xg0,
                                                float* __restrict__ h_out) {
    __shared__ __align__(16) float As[16][BM + 4];
    __shared__ __align__(16) float Bs[16][BN];
    __shared__ __align__(16) float Cs[BM][BN];

    const int tid = threadIdx.x;
    const int row0 = blockIdx.y * BM;
    const int n0 = blockIdx.x * BN;
    // loaders: tid<256 -> A float4 ; all threads -> B flat strided (1280 floats)
    const int lr = (tid & 255) >> 2;
    const int lk = (tid & 3) << 2;
    // compute: 2 rows x 5 cols
    const int tm = tid & 31;                  // rows tm*2, tm*2+1
    const int tn = tid >> 5;                  // cols tn + 16j

    float acc[2][5];
#pragma unroll
    for (int i = 0; i < 2; i++)
#pragma unroll
        for (int j = 0; j < 5; j++) acc[i][j] = 0.f;

    float* Bflat = &Bs[0][0];

    if (tid < 256) {
        float4 av = *reinterpret_cast<const float4*>(A + (size_t)(row0 + lr) * HSZ + lk);
        As[lk + 0][lr] = av.x; As[lk + 1][lr] = av.y;
        As[lk + 2][lr] = av.z; As[lk + 3][lr] = av.w;
    }
    {
        int i0 = tid, i1 = tid + 512;
        Bflat[i0] = g_WdecT[(size_t)(i0 / BN) * NC + n0 + (i0 % BN)];
        Bflat[i1] = g_WdecT[(size_t)(i1 / BN) * NC + n0 + (i1 % BN)];
        if (tid < 256) {
            int i2 = tid + 1024;
            Bflat[i2] = g_WdecT[(size_t)(i2 / BN) * NC + n0 + (i2 % BN)];
        }
    }
    __syncthreads();

    const int NKC = HSZ / 16;
    for (int kc = 0; kc < NKC; kc++) {
        float4 av;
        float bv0, bv1, bv2;
        if (kc + 1 < NKC) {
            int k0 = (kc + 1) * 16;
            if (tid < 256) {
                av = *reinterpret_cast<const float4*>(A + (size_t)(row0 + lr) * HSZ + k0 + lk);
                int i2 = tid + 1024;
                bv2 = g_WdecT[(size_t)(k0 + i2 / BN) * NC + n0 + (i2 % BN)];
            }
            int i0 = tid, i1 = tid + 512;
            bv0 = g_WdecT[(size_t)(k0 + i0 / BN) * NC + n0 + (i0 % BN)];
            bv1 = g_WdecT[(size_t)(k0 + i1 / BN) * NC + n0 + (i1 % BN)];
        }
#pragma unroll
        for (int k = 0; k < 16; k++) {
            float2 a2 = *reinterpret_cast<const float2*>(&As[k][tm * 2]);
            float ar[2] = {a2.x, a2.y};
            float br[5];
#pragma unroll
            for (int j = 0; j < 5; j++) br[j] = Bs[k][tn + 16 * j];
#pragma unroll
            for (int i = 0; i < 2; i++)
#pragma unroll
                for (int j = 0; j < 5; j++) acc[i][j] = fmaf(ar[i], br[j], acc[i][j]);
        }
        __syncthreads();
        if (kc + 1 < NKC) {
            if (tid < 256) {
                As[lk + 0][lr] = av.x; As[lk + 1][lr] = av.y;
                As[lk + 2][lr] = av.z; As[lk + 3][lr] = av.w;
                Bflat[tid + 1024] = bv2;
            }
            Bflat[tid] = bv0;
            Bflat[tid + 512] = bv1;
            __syncthreads();
        }
    }

#pragma unroll
    for (int i = 0; i < 2; i++) {
        int b = row0 + tm * 2 + i;
#pragma unroll
        for (int j = 0; j < 5; j++) {
            int n = n0 + tn + 16 * j;
            if (n < GSZ) {
                if (do_cell) Cs[tm * 2 + i][tn + 16 * j] = acc[i][j];
                else         g_C[(size_t)b * GSZ + n] = acc[i][j];
            } else if (dst2) {
                dst2[(size_t)b * HSZ + (n - GSZ)] = __fadd_rn(acc[i][j], bias2[n - GSZ]);
            }
        }
    }

    if (do_cell) {
        __syncthreads();
        int gate_cols = (n0 < GSZ) ? min(GSZ - n0, BN) : 0;
        int nquads = gate_cols >> 2;
        int items = BM * nquads;
        for (int it = tid; it < items; it += 512) {
            int r = it / nquads, qi = it - r * nquads;
            int b = row0 + r;
            int hh = (n0 >> 2) + qi;
            const float* xr = xg0 + n0 + 4 * qi;
            int c4 = 4 * qi;
            float gi = __fadd_rn(xr[0], Cs[r][c4 + 0]);
            float gf = __fadd_rn(xr[1], Cs[r][c4 + 1]);
            float gg = __fadd_rn(xr[2], Cs[r][c4 + 2]);
            float go = __fadd_rn(xr[3], Cs[r][c4 + 3]);
            float si = sigf(gi), sf = sigf(gf), so = sigf(go);
            float tg = xtanh(gg);
            int idx = b * HSZ + hh;
            float cn = __fadd_rn(__fmul_rn(sf, g_c[idx]), __fmul_rn(si, tg));
            g_c[idx] = cn;
            h_out[idx] = __fmul_rn(so, xtanh(cn));
        }
    }
}

// ---------- attention phase 1: u dots, 2048 blocks ----------
__global__ void __launch_bounds__(256) attn_u_kernel(const float* __restrict__ V) {
    int b = blockIdx.x, qq = blockIdx.y;
    int tid = threadIdx.x, lane = tid & 31, w = tid >> 5;
    __shared__ float qs[HSZ];
    __shared__ float Vs[HSZ];
    for (int i = tid; i < HSZ; i += 256) {
        qs[i] = g_q[(size_t)b * HSZ + i];
        Vs[i] = V[i];
    }
    __syncthreads();
#pragma unroll
    for (int m = 0; m < 2; m++) {
        int s = qq * 16 + w + 8 * m;
        const float* pr = g_proj + ((size_t)b * SSZ + s) * HSZ;
        float acc = 0.f;
        for (int h = lane; h < HSZ; h += 32)
            acc = fmaf(xtanh(__fadd_rn(pr[h], qs[h])), Vs[h], acc);
#pragma unroll
        for (int o = 16; o; o >>= 1)
            acc = __fadd_rn(acc, __shfl_xor_sync(0xffffffffu, acc, o));
        if (lane == 0) g_us[b * SSZ + s] = g_mask[b * SSZ + s] ? acc : -10000.0f;
    }
}

// ---------- attention phase 2: softmax + argmax + mask + fused decoder cell ----------
__global__ void __launch_bounds__(128) attn_fin_kernel(int step,
                                                       float* __restrict__ out_probs,
                                                       float* __restrict__ out_idx,
                                                       float* __restrict__ h_out) {
    int b = blockIdx.x;
    int tid = threadIdx.x, lane = tid & 31, w = tid >> 5;
    __shared__ float us[SSZ];
    __shared__ float es[SSZ];
    __shared__ float ps[SSZ];
    __shared__ float s_mx, s_sum;
    __shared__ int s_idx;

    us[tid] = g_us[b * SSZ + tid];
    __syncthreads();

    if (w == 0) {
        float mv = fmaxf(us[lane], fmaxf(us[lane + 32], fmaxf(us[lane + 64], us[lane + 96])));
#pragma unroll
        for (int o = 16; o; o >>= 1) mv = fmaxf(mv, __shfl_xor_sync(0xffffffffu, mv, o));
        if (lane == 0) s_mx = mv;
    }
    __syncthreads();

    es[tid] = expf(__fadd_rn(us[tid], -s_mx));
    __syncthreads();

    if (w == 0) {
        float sv = __fadd_rn(__fadd_rn(es[lane], es[lane + 32]),
                             __fadd_rn(es[lane + 64], es[lane + 96]));
#pragma unroll
        for (int o = 16; o; o >>= 1)
            sv = __fadd_rn(sv, __shfl_xor_sync(0xffffffffu, sv, o));
        if (lane == 0) s_sum = sv;
    }
    __syncthreads();

    {
        float p = __fdiv_rn(es[tid], s_sum);
        ps[tid] = p;
        out_probs[((size_t)step * BSZ + b) * SSZ + tid] = p;
    }
    __syncthreads();

    if (w == 0) {
        float bv = -1.0f;
        int bi = 0;
#pragma unroll
        for (int k = 0; k < 4; k++) {
            int s = lane + 32 * k;
            float v = ps[s];
            if (v > bv) { bv = v; bi = s; }
        }
#pragma unroll
        for (int o = 16; o; o >>= 1) {
            float ov = __shfl_xor_sync(0xffffffffu, bv, o);
            int oi = __shfl_xor_sync(0xffffffffu, bi, o);
            if (ov > bv || (ov == bv && oi < bi)) { bv = ov; bi = oi; }
        }
        if (lane == 0) s_idx = bi;
    }
    __syncthreads();

    int bi = s_idx;
    if (tid == 0) {
        g_mask[b * SSZ + bi] = 0;
        if (out_idx) out_idx[(size_t)b * SSZ + step] = (float)bi;
    }

    if (h_out) {
        const float* Cb = g_C + (size_t)b * GSZ;
        const float* xr = g_xg_dec + ((size_t)b * SSZ + bi) * GSZ;
#pragma unroll
        for (int j = 0; j < 4; j++) {
            int hh = tid + 128 * j;
            int n4 = 4 * hh;
            int idx = b * HSZ + hh;
            float gi = __fadd_rn(xr[n4 + 0], Cb[n4 + 0]);
            float gf = __fadd_rn(xr[n4 + 1], Cb[n4 + 1]);
            float gg = __fadd_rn(xr[n4 + 2], Cb[n4 + 2]);
            float go = __fadd_rn(xr[n4 + 3], Cb[n4 + 3]);
            float si = sigf(gi), sf = sigf(gf), so = sigf(go);
            float tg = xtanh(gg);
            float cn = __fadd_rn(__fmul_rn(sf, g_c[idx]), __fmul_rn(si, tg));
            g_c[idx] = cn;
            h_out[idx] = __fmul_rn(so, xtanh(cn));
        }
    }
}

// ---------- host ----------
extern "C" void kernel_launch(void* const* d_in, const int* in_sizes, int n_in,
                              void* d_out, int out_size) {
    const float* inputs  = (const float*)d_in[0];
    const float* emb_W   = (const float*)d_in[2];
    const float* emb_b   = (const float*)d_in[3];
    const float* enc_Wih = (const float*)d_in[4];
    const float* enc_Whh = (const float*)d_in[5];
    const float* enc_bih = (const float*)d_in[6];
    const float* enc_bhh = (const float*)d_in[7];
    const float* h0      = (const float*)d_in[8];
    const float* c0      = (const float*)d_in[9];
    const float* dec0    = (const float*)d_in[10];
    const float* dec_Wih = (const float*)d_in[11];
    const float* dec_Whh = (const float*)d_in[12];
    const float* dec_bih = (const float*)d_in[13];
    const float* dec_bhh = (const float*)d_in[14];
    const float* W1      = (const float*)d_in[15];
    const float* b1      = (const float*)d_in[16];
    const float* W2      = (const float*)d_in[17];
    const float* b2      = (const float*)d_in[18];
    const float* V       = (const float*)d_in[19];

    float *phall, *phdec, *pq, *pxg_enc, *pxg0;
    cudaGetSymbolAddress((void**)&phall,   g_hall);
    cudaGetSymbolAddress((void**)&phdec,   g_hdec);
    cudaGetSymbolAddress((void**)&pq,      g_q);
    cudaGetSymbolAddress((void**)&pxg_enc, g_xg_enc);
    cudaGetSymbolAddress((void**)&pxg0,    g_xg0);

    float* out_probs = (float*)d_out;
    const size_t PROBS_N = (size_t)SSZ * BSZ * SSZ;
    float* out_idx = ((size_t)out_size >= PROBS_N + (size_t)BSZ * SSZ)
                         ? out_probs + PROBS_N : nullptr;

    dim3 ge(GSZ / 64, BSZ / 64);
    dim3 gd(NC / BN, BSZ / BM);
    dim3 gp(HSZ / 64, BSZ * SSZ / 64);
    dim3 gx(NB2 / 64, BSZ * SSZ / 64);
    dim3 ga(BSZ, 8);

    const size_t HB = (size_t)BSZ * HSZ;

    init_kernel<<<(BSZ * HSZ + 255) / 256, 256>>>(h0, c0, inputs);
    transpose_kernel<<<(HSZ * NC + 255) / 256, 256>>>(enc_Whh, W1, dec_Whh, W2);
    emb_kernel<<<(BSZ * SSZ * ESZ + 255) / 256, 256>>>(inputs, emb_W, emb_b);
    gemm_enc<<<ge, 512>>>(phall, 0, nullptr, nullptr);   // profiled slot
    wiht_kernel<<<(ESZ * NB2 + 255) / 256, 256>>>(enc_Wih, dec_Wih);
    xg_gemm<<<gx, 256>>>(enc_bih, enc_bhh, dec_bih, dec_bhh);
    xg0_kernel<<<GSZ / 256, 256>>>(dec_Wih, dec_bih, dec_bhh, dec0);
    cell0_kernel<<<BSZ * HSZ / 256, 256>>>(phall + HB, pxg_enc);

    for (int t = 1; t < SSZ; t++)
        gemm_enc<<<ge, 512>>>(phall + (size_t)t * HB, 1,
                              pxg_enc + (size_t)t * GSZ, phall + (size_t)(t + 1) * HB);

    proj_gemm<<<gp, 256>>>(b1);

    float* hb[2] = {phall + (size_t)SSZ * HB, phdec};
    int cur = 0;
    for (int t = 0; t < SSZ; t++) {
        if (t == 0) {
            gemm_dec<<<gd, 512>>>(hb[cur], nullptr, b2, 1, pxg0, hb[cur ^ 1]);
        } else {
            gemm_dec<<<gd, 512>>>(hb[cur], pq, b2, 0, nullptr, nullptr);
            attn_u_kernel<<<ga, 256>>>(V);
            attn_fin_kernel<<<BSZ, 128>>>(t - 1, out_probs, out_idx, hb[cur ^ 1]);
        }
        cur ^= 1;
    }
    gemm_dec<<<gd, 512>>>(hb[cur], pq, b2, 0, nullptr, nullptr);
    attn_u_kernel<<<ga, 256>>>(V);
    attn_fin_kernel<<<BSZ, 128>>>(SSZ - 1, out_probs, out_idx, nullptr);
}

// round 17
// speedup vs baseline: 1.1692x; 1.1692x over previous
#include <cuda_runtime.h>
#include <math.h>
#include <stddef.h>

#define BSZ 256
#define SSZ 128
#define ESZ 256
#define HSZ 512
#define GSZ 2048   // 4*H (interleaved gate cols)
#define NC  2560   // decoder weights: 2048 interleaved gates | 512 (W2T)
#define NB2 4096

// ---------- device scratch ----------
__device__ float  g_WencG[HSZ * GSZ];
__device__ float  g_W1T[HSZ * HSZ];
__device__ float  g_WdecT[HSZ * NC];
__device__ float  g_WihT[ESZ * NB2];
__device__ float  g_emb[(size_t)BSZ * SSZ * ESZ];
__device__ float  g_xg_enc[(size_t)BSZ * SSZ * GSZ];
__device__ float  g_xg_dec[(size_t)BSZ * SSZ * GSZ];
__device__ float  g_proj[(size_t)BSZ * SSZ * HSZ];
__device__ float  g_hall[(size_t)(SSZ + 1) * BSZ * HSZ];
__device__ float  g_hdec[BSZ * HSZ];
__device__ float  g_C[BSZ * GSZ];
__device__ float  g_c[BSZ * HSZ];
__device__ float  g_q[BSZ * HSZ];
__device__ float  g_xg0[GSZ];
__device__ float  g_us[BSZ * SSZ];
__device__ int    g_mask[BSZ * SSZ];

// ---------- frozen numerics ----------
__device__ __forceinline__ float xtanh(float x) { return tanhf(x); }
__device__ __forceinline__ float sigf(float x) {
    return __fdiv_rn(1.0f, __fadd_rn(1.0f, expf(-x)));
}
__device__ __forceinline__ int deint(int n) { return (n & 3) * HSZ + (n >> 2); }

// ---------- packed dual-lane FMA (per-lane IEEE fp32 fma -> bitwise identical) ----------
__device__ __forceinline__ unsigned long long pack2(float lo, float hi) {
    unsigned long long r;
    asm("mov.b64 %0, {%1, %2};" : "=l"(r) : "f"(lo), "f"(hi));
    return r;
}
__device__ __forceinline__ void unpack2(unsigned long long v, float& lo, float& hi) {
    asm("mov.b64 {%0, %1}, %2;" : "=f"(lo), "=f"(hi) : "l"(v));
}
__device__ __forceinline__ void ffma2(unsigned long long& d, unsigned long long a, unsigned long long b) {
    asm("fma.rn.f32x2 %0, %1, %2, %3;" : "=l"(d) : "l"(a), "l"(b), "l"(d));
}

// ---------- state init ----------
__global__ void init_kernel(const float* __restrict__ h0, const float* __restrict__ c0,
                            const float* __restrict__ inputs) {
    int i = blockIdx.x * blockDim.x + threadIdx.x;
    if (i < BSZ * HSZ) {
        g_hall[i] = h0[i & (HSZ - 1)];
        g_c[i]    = c0[i & (HSZ - 1)];
    }
    if (i < BSZ * SSZ) g_mask[i] = (inputs[(size_t)i * 2] > 0.0f) ? 1 : 0;
}

// ---------- weight transposes ----------
__global__ void transpose_kernel(const float* __restrict__ encWhh, const float* __restrict__ W1,
                                 const float* __restrict__ decWhh, const float* __restrict__ W2) {
    int i = blockIdx.x * blockDim.x + threadIdx.x;
    if (i >= HSZ * NC) return;
    int k = i / NC, n = i % NC;
    if (n < GSZ) {
        int orig = deint(n);
        g_WencG[k * GSZ + n] = encWhh[orig * HSZ + k];
        g_WdecT[i] = decWhh[orig * HSZ + k];
    } else {
        int n2 = n - GSZ;
        g_W1T[k * HSZ + n2] = W1[n2 * HSZ + k];
        g_WdecT[i] = W2[n2 * HSZ + k];
    }
}
__global__ void wiht_kernel(const float* __restrict__ encWih, const float* __restrict__ decWih) {
    int i = blockIdx.x * blockDim.x + threadIdx.x;
    if (i >= ESZ * NB2) return;
    int k = i / NB2, n = i % NB2;
    float v;
    if (n < GSZ) v = encWih[deint(n) * ESZ + k];
    else         v = decWih[deint(n - GSZ) * ESZ + k];
    g_WihT[i] = v;
}

// ---------- emb ----------
__global__ void emb_kernel(const float* __restrict__ inputs, const float* __restrict__ embW,
                           const float* __restrict__ embB) {
    int i = blockIdx.x * blockDim.x + threadIdx.x;
    if (i >= BSZ * SSZ * ESZ) return;
    int e = i % ESZ, bs = i / ESZ;
    float in0 = inputs[(size_t)bs * 2], in1 = inputs[(size_t)bs * 2 + 1];
    float mm = fmaf(in1, embW[2 * e + 1], __fmul_rn(in0, embW[2 * e]));
    g_emb[i] = __fadd_rn(mm, embB[e]);
}

// ---------- decoder step-0 input gates ----------
__global__ void xg0_kernel(const float* __restrict__ decWih, const float* __restrict__ dbih,
                           const float* __restrict__ dbhh, const float* __restrict__ dec0) {
    int n = blockIdx.x * blockDim.x + threadIdx.x;
    if (n >= GSZ) return;
    int orig = deint(n);
    float acc = 0.f;
    for (int e = 0; e < ESZ; e++) acc = fmaf(dec0[e], decWih[orig * ESZ + e], acc);
    g_xg0[n] = __fadd_rn(__fadd_rn(acc, dbih[orig]), dbhh[orig]);
}

// ---------- xg precompute GEMM (one-shot) ----------
__global__ void __launch_bounds__(256) xg_gemm(const float* __restrict__ ebih, const float* __restrict__ ebhh,
                                               const float* __restrict__ dbih, const float* __restrict__ dbhh) {
    __shared__ __align__(16) float As[16][64 + 4];
    __shared__ __align__(16) float Bs[16][64];
    const int tid = threadIdx.x;
    const int row0 = blockIdx.y * 64;
    const int n0 = blockIdx.x * 64;
    const int lr = tid >> 2, lk = (tid & 3) << 2;
    const int bk = tid >> 4, bn = (tid & 15) << 2;
    const int tm = tid & 15, tn = tid >> 4;

    unsigned long long acc2[4][2];
#pragma unroll
    for (int i = 0; i < 4; i++)
#pragma unroll
        for (int j = 0; j < 2; j++) acc2[i][j] = pack2(0.f, 0.f);

    {
        float4 av = *reinterpret_cast<const float4*>(g_emb + (size_t)(row0 + lr) * ESZ + lk);
        As[lk + 0][lr] = av.x; As[lk + 1][lr] = av.y;
        As[lk + 2][lr] = av.z; As[lk + 3][lr] = av.w;
        *reinterpret_cast<float4*>(&Bs[bk][bn]) =
            *reinterpret_cast<const float4*>(g_WihT + (size_t)bk * NB2 + n0 + bn);
    }
    __syncthreads();

    const int NKC = ESZ / 16;
    for (int kc = 0; kc < NKC; kc++) {
        float4 av; float4 bv;
        if (kc + 1 < NKC) {
            int k0 = (kc + 1) * 16;
            av = *reinterpret_cast<const float4*>(g_emb + (size_t)(row0 + lr) * ESZ + k0 + lk);
            bv = *reinterpret_cast<const float4*>(g_WihT + (size_t)(k0 + bk) * NB2 + n0 + bn);
        }
#pragma unroll
        for (int k = 0; k < 16; k++) {
            float4 a4 = *reinterpret_cast<const float4*>(&As[k][tm * 4]);
            float4 b4 = *reinterpret_cast<const float4*>(&Bs[k][tn * 4]);
            float ar[4] = {a4.x, a4.y, a4.z, a4.w};
            unsigned long long bp0 = pack2(b4.x, b4.y);
            unsigned long long bp1 = pack2(b4.z, b4.w);
#pragma unroll
            for (int i = 0; i < 4; i++) {
                unsigned long long ap = pack2(ar[i], ar[i]);
                ffma2(acc2[i][0], ap, bp0);
                ffma2(acc2[i][1], ap, bp1);
            }
        }
        __syncthreads();
        if (kc + 1 < NKC) {
            As[lk + 0][lr] = av.x; As[lk + 1][lr] = av.y;
            As[lk + 2][lr] = av.z; As[lk + 3][lr] = av.w;
            *reinterpret_cast<float4*>(&Bs[bk][bn]) = bv;
            __syncthreads();
        }
    }

#pragma unroll
    for (int i = 0; i < 4; i++) {
        size_t row = row0 + tm * 4 + i;
        float a0, a1, a2, a3;
        unpack2(acc2[i][0], a0, a1);
        unpack2(acc2[i][1], a2, a3);
        float accv[4] = {a0, a1, a2, a3};
#pragma unroll
        for (int j = 0; j < 4; j++) {
            int n = n0 + tn * 4 + j;
            if (n < GSZ) {
                int orig = deint(n);
                g_xg_enc[row * GSZ + n] = __fadd_rn(__fadd_rn(accv[j], ebih[orig]), ebhh[orig]);
            } else {
                int nd = n - GSZ;
                int orig = deint(nd);
                g_xg_dec[row * GSZ + nd] = __fadd_rn(__fadd_rn(accv[j], dbih[orig]), dbhh[orig]);
            }
        }
    }
}

// ---------- step GEMM [256,2048] = h @ W (ldw param) (+ optional fused cell) ----------
// round-15 geometry: 256 threads, 64x64 tile, 4x4/thread, f32x2.
// Triggers PDL completion at start: produces nothing the PDL-dependent attn_u reads.
__global__ void __launch_bounds__(256) gemm_step(const float* __restrict__ A,
                                                 const float* __restrict__ W,
                                                 int ldw,
                                                 int do_cell,
                                                 const float* __restrict__ xg,
                                                 size_t xgb,
                                                 float* __restrict__ h_out) {
#if __CUDA_ARCH__ >= 900
    cudaTriggerProgrammaticLaunchCompletion();
#endif
    __shared__ __align__(16) float As[16][64 + 4];
    __shared__ __align__(16) float Bs[16][64];
    __shared__ __align__(16) float Cs[64][64];

    const int tid = threadIdx.x;
    const int row0 = blockIdx.y * 64;
    const int n0 = blockIdx.x * 64;
    const int lr = tid >> 2, lk = (tid & 3) << 2;
    const int bk = tid >> 4, bn = (tid & 15) << 2;
    const int tm = tid & 15, tn = tid >> 4;

    unsigned long long acc2[4][2];
#pragma unroll
    for (int i = 0; i < 4; i++)
#pragma unroll
        for (int j = 0; j < 2; j++) acc2[i][j] = pack2(0.f, 0.f);

    {
        float4 av = *reinterpret_cast<const float4*>(A + (size_t)(row0 + lr) * HSZ + lk);
        As[lk + 0][lr] = av.x; As[lk + 1][lr] = av.y;
        As[lk + 2][lr] = av.z; As[lk + 3][lr] = av.w;
        *reinterpret_cast<float4*>(&Bs[bk][bn]) =
            *reinterpret_cast<const float4*>(W + (size_t)bk * ldw + n0 + bn);
    }
    __syncthreads();

    const int NKC = HSZ / 16;  // 32
    for (int kc = 0; kc < NKC; kc++) {
        float4 av; float4 bv;
        if (kc + 1 < NKC) {
            int k0 = (kc + 1) * 16;
            av = *reinterpret_cast<const float4*>(A + (size_t)(row0 + lr) * HSZ + k0 + lk);
            bv = *reinterpret_cast<const float4*>(W + (size_t)(k0 + bk) * ldw + n0 + bn);
        }
#pragma unroll
        for (int k = 0; k < 16; k++) {
            float4 a4 = *reinterpret_cast<const float4*>(&As[k][tm * 4]);
            float4 b4 = *reinterpret_cast<const float4*>(&Bs[k][tn * 4]);
            float ar[4] = {a4.x, a4.y, a4.z, a4.w};
            unsigned long long bp0 = pack2(b4.x, b4.y);
            unsigned long long bp1 = pack2(b4.z, b4.w);
#pragma unroll
            for (int i = 0; i < 4; i++) {
                unsigned long long ap = pack2(ar[i], ar[i]);
                ffma2(acc2[i][0], ap, bp0);
                ffma2(acc2[i][1], ap, bp1);
            }
        }
        __syncthreads();
        if (kc + 1 < NKC) {
            As[lk + 0][lr] = av.x; As[lk + 1][lr] = av.y;
            As[lk + 2][lr] = av.z; As[lk + 3][lr] = av.w;
            *reinterpret_cast<float4*>(&Bs[bk][bn]) = bv;
            __syncthreads();
        }
    }

    if (!do_cell) {
#pragma unroll
        for (int i = 0; i < 4; i++) {
            int b = row0 + tm * 4 + i;
            float a0, a1, a2, a3;
            unpack2(acc2[i][0], a0, a1);
            unpack2(acc2[i][1], a2, a3);
            g_C[(size_t)b * GSZ + n0 + tn * 4 + 0] = a0;
            g_C[(size_t)b * GSZ + n0 + tn * 4 + 1] = a1;
            g_C[(size_t)b * GSZ + n0 + tn * 4 + 2] = a2;
            g_C[(size_t)b * GSZ + n0 + tn * 4 + 3] = a3;
        }
        return;
    }

#pragma unroll
    for (int i = 0; i < 4; i++) {
        float a0, a1, a2, a3;
        unpack2(acc2[i][0], a0, a1);
        unpack2(acc2[i][1], a2, a3);
        Cs[tm * 4 + i][tn * 4 + 0] = a0;
        Cs[tm * 4 + i][tn * 4 + 1] = a1;
        Cs[tm * 4 + i][tn * 4 + 2] = a2;
        Cs[tm * 4 + i][tn * 4 + 3] = a3;
    }
    __syncthreads();

    for (int it = tid; it < 64 * 16; it += 256) {
        int r = it >> 4, qi = it & 15;
        int b = row0 + r;
        int hh = (n0 >> 2) + qi;
        const float* xr = xg + (size_t)b * xgb + n0 + 4 * qi;
        int c4 = 4 * qi;
        float gi = __fadd_rn(xr[0], Cs[r][c4 + 0]);
        float gf = __fadd_rn(xr[1], Cs[r][c4 + 1]);
        float gg = __fadd_rn(xr[2], Cs[r][c4 + 2]);
        float go = __fadd_rn(xr[3], Cs[r][c4 + 3]);
        float si = sigf(gi), sf = sigf(gf), so = sigf(go);
        float tg = xtanh(gg);
        int idx = b * HSZ + hh;
        float cn = __fadd_rn(__fmul_rn(sf, g_c[idx]), __fmul_rn(si, tg));
        g_c[idx] = cn;
        h_out[idx] = __fmul_rn(so, xtanh(cn));
    }
}

// ---------- q GEMM [256,512] = h @ W2T + b2 -> g_q ----------
__global__ void __launch_bounds__(256) q_gemm(const float* __restrict__ A,
                                              const float* __restrict__ b2) {
    __shared__ __align__(16) float As[16][64 + 4];
    __shared__ __align__(16) float Bs[16][64];
    const float* W = g_WdecT + GSZ;   // cols 2048.., row stride NC
    const int tid = threadIdx.x;
    const int row0 = blockIdx.y * 64;
    const int n0 = blockIdx.x * 64;
    const int lr = tid >> 2, lk = (tid & 3) << 2;
    const int bk = tid >> 4, bn = (tid & 15) << 2;
    const int tm = tid & 15, tn = tid >> 4;

    unsigned long long acc2[4][2];
#pragma unroll
    for (int i = 0; i < 4; i++)
#pragma unroll
        for (int j = 0; j < 2; j++) acc2[i][j] = pack2(0.f, 0.f);

    {
        float4 av = *reinterpret_cast<const float4*>(A + (size_t)(row0 + lr) * HSZ + lk);
        As[lk + 0][lr] = av.x; As[lk + 1][lr] = av.y;
        As[lk + 2][lr] = av.z; As[lk + 3][lr] = av.w;
        *reinterpret_cast<float4*>(&Bs[bk][bn]) =
            *reinterpret_cast<const float4*>(W + (size_t)bk * NC + n0 + bn);
    }
    __syncthreads();

    const int NKC = HSZ / 16;
    for (int kc = 0; kc < NKC; kc++) {
        float4 av; float4 bv;
        if (kc + 1 < NKC) {
            int k0 = (kc + 1) * 16;
            av = *reinterpret_cast<const float4*>(A + (size_t)(row0 + lr) * HSZ + k0 + lk);
            bv = *reinterpret_cast<const float4*>(W + (size_t)(k0 + bk) * NC + n0 + bn);
        }
#pragma unroll
        for (int k = 0; k < 16; k++) {
            float4 a4 = *reinterpret_cast<const float4*>(&As[k][tm * 4]);
            float4 b4 = *reinterpret_cast<const float4*>(&Bs[k][tn * 4]);
            float ar[4] = {a4.x, a4.y, a4.z, a4.w};
            unsigned long long bp0 = pack2(b4.x, b4.y);
            unsigned long long bp1 = pack2(b4.z, b4.w);
#pragma unroll
            for (int i = 0; i < 4; i++) {
                unsigned long long ap = pack2(ar[i], ar[i]);
                ffma2(acc2[i][0], ap, bp0);
                ffma2(acc2[i][1], ap, bp1);
            }
        }
        __syncthreads();
        if (kc + 1 < NKC) {
            As[lk + 0][lr] = av.x; As[lk + 1][lr] = av.y;
            As[lk + 2][lr] = av.z; As[lk + 3][lr] = av.w;
            *reinterpret_cast<float4*>(&Bs[bk][bn]) = bv;
            __syncthreads();
        }
    }

#pragma unroll
    for (int i = 0; i < 4; i++) {
        int b = row0 + tm * 4 + i;
        float a0, a1, a2, a3;
        unpack2(acc2[i][0], a0, a1);
        unpack2(acc2[i][1], a2, a3);
        float accv[4] = {a0, a1, a2, a3};
#pragma unroll
        for (int j = 0; j < 4; j++) {
            int n = n0 + tn * 4 + j;
            g_q[(size_t)b * HSZ + n] = __fadd_rn(accv[j], b2[n]);
        }
    }
}

// ---------- standalone encoder cell (t=0) ----------
__global__ void __launch_bounds__(256) cell0_kernel(float* __restrict__ h_out,
                                                    const float* __restrict__ xg) {
    int idx = blockIdx.x * blockDim.x + threadIdx.x;
    int b = idx >> 9, hh = idx & (HSZ - 1);
    int n4 = 4 * hh;
    const float* Cb = g_C + (size_t)b * GSZ;
    const float* xr = xg + (size_t)b * ((size_t)SSZ * GSZ);
    float gi = __fadd_rn(xr[n4 + 0], Cb[n4 + 0]);
    float gf = __fadd_rn(xr[n4 + 1], Cb[n4 + 1]);
    float gg = __fadd_rn(xr[n4 + 2], Cb[n4 + 2]);
    float go = __fadd_rn(xr[n4 + 3], Cb[n4 + 3]);
    float si = sigf(gi), sf = sigf(gf), so = sigf(go);
    float tg = xtanh(gg);
    float cn = __fadd_rn(__fmul_rn(sf, g_c[idx]), __fmul_rn(si, tg));
    g_c[idx] = cn;
    h_out[idx] = __fmul_rn(so, xtanh(cn));
}

// ---------- big proj GEMM (one-shot) ----------
__global__ void __launch_bounds__(256) proj_gemm(const float* __restrict__ b1) {
    __shared__ __align__(16) float As[16][64 + 4];
    __shared__ __align__(16) float Bs[16][64];
    const float* A = g_hall + (size_t)BSZ * HSZ;
    const int tid = threadIdx.x;
    const int row0 = blockIdx.y * 64;
    const int n0 = blockIdx.x * 64;
    const int lr = tid >> 2, lk = (tid & 3) << 2;
    const int bk = tid >> 4, bn = (tid & 15) << 2;
    const int tm = tid & 15, tn = tid >> 4;

    unsigned long long acc2[4][2];
#pragma unroll
    for (int i = 0; i < 4; i++)
#pragma unroll
        for (int j = 0; j < 2; j++) acc2[i][j] = pack2(0.f, 0.f);

    {
        float4 av = *reinterpret_cast<const float4*>(A + (size_t)(row0 + lr) * HSZ + lk);
        As[lk + 0][lr] = av.x; As[lk + 1][lr] = av.y;
        As[lk + 2][lr] = av.z; As[lk + 3][lr] = av.w;
        *reinterpret_cast<float4*>(&Bs[bk][bn]) =
            *reinterpret_cast<const float4*>(g_W1T + (size_t)bk * HSZ + n0 + bn);
    }
    __syncthreads();

    const int NKC = HSZ / 16;
    for (int kc = 0; kc < NKC; kc++) {
        float4 av; float4 bv;
        if (kc + 1 < NKC) {
            int k0 = (kc + 1) * 16;
            av = *reinterpret_cast<const float4*>(A + (size_t)(row0 + lr) * HSZ + k0 + lk);
            bv = *reinterpret_cast<const float4*>(g_W1T + (size_t)(k0 + bk) * HSZ + n0 + bn);
        }
#pragma unroll
        for (int k = 0; k < 16; k++) {
            float4 a4 = *reinterpret_cast<const float4*>(&As[k][tm * 4]);
            float4 b4 = *reinterpret_cast<const float4*>(&Bs[k][tn * 4]);
            float ar[4] = {a4.x, a4.y, a4.z, a4.w};
            unsigned long long bp0 = pack2(b4.x, b4.y);
            unsigned long long bp1 = pack2(b4.z, b4.w);
#pragma unroll
            for (int i = 0; i < 4; i++) {
                unsigned long long ap = pack2(ar[i], ar[i]);
                ffma2(acc2[i][0], ap, bp0);
                ffma2(acc2[i][1], ap, bp1);
            }
        }
        __syncthreads();
        if (kc + 1 < NKC) {
            As[lk + 0][lr] = av.x; As[lk + 1][lr] = av.y;
            As[lk + 2][lr] = av.z; As[lk + 3][lr] = av.w;
            *reinterpret_cast<float4*>(&Bs[bk][bn]) = bv;
            __syncthreads();
        }
    }

#pragma unroll
    for (int i = 0; i < 4; i++) {
        int r = row0 + tm * 4 + i;
        int s = r >> 8, b = r & (BSZ - 1);
        size_t orow = ((size_t)b * SSZ + s) * HSZ;
        float a0, a1, a2, a3;
        unpack2(acc2[i][0], a0, a1);
        unpack2(acc2[i][1], a2, a3);
        float accv[4] = {a0, a1, a2, a3};
#pragma unroll
        for (int j = 0; j < 4; j++) {
            int n = n0 + tn * 4 + j;
            g_proj[orow + n] = __fadd_rn(accv[j], b1[n]);
        }
    }
}

// ---------- attention phase 1: u dots, 2048 blocks ----------
__global__ void __launch_bounds__(256) attn_u_kernel(const float* __restrict__ V) {
    int b = blockIdx.x, qq = blockIdx.y;
    int tid = threadIdx.x, lane = tid & 31, w = tid >> 5;
    __shared__ float qs[HSZ];
    __shared__ float Vs[HSZ];
    for (int i = tid; i < HSZ; i += 256) {
        qs[i] = g_q[(size_t)b * HSZ + i];
        Vs[i] = V[i];
    }
    __syncthreads();
#pragma unroll
    for (int m = 0; m < 2; m++) {
        int s = qq * 16 + w + 8 * m;
        const float* pr = g_proj + ((size_t)b * SSZ + s) * HSZ;
        float acc = 0.f;
        for (int h = lane; h < HSZ; h += 32)
            acc = fmaf(xtanh(__fadd_rn(pr[h], qs[h])), Vs[h], acc);
#pragma unroll
        for (int o = 16; o; o >>= 1)
            acc = __fadd_rn(acc, __shfl_xor_sync(0xffffffffu, acc, o));
        if (lane == 0) g_us[b * SSZ + s] = g_mask[b * SSZ + s] ? acc : -10000.0f;
    }
}

// ---------- attention phase 2: softmax + argmax + mask + fused decoder cell ----------
__global__ void __launch_bounds__(128) attn_fin_kernel(int step,
                                                       float* __restrict__ out_probs,
                                                       float* __restrict__ out_idx,
                                                       float* __restrict__ h_out) {
    int b = blockIdx.x;
    int tid = threadIdx.x, lane = tid & 31, w = tid >> 5;
    __shared__ float us[SSZ];
    __shared__ float es[SSZ];
    __shared__ float ps[SSZ];
    __shared__ float s_mx, s_sum;
    __shared__ int s_idx;

    us[tid] = g_us[b * SSZ + tid];
    __syncthreads();

    if (w == 0) {
        float mv = fmaxf(us[lane], fmaxf(us[lane + 32], fmaxf(us[lane + 64], us[lane + 96])));
#pragma unroll
        for (int o = 16; o; o >>= 1) mv = fmaxf(mv, __shfl_xor_sync(0xffffffffu, mv, o));
        if (lane == 0) s_mx = mv;
    }
    __syncthreads();

    es[tid] = expf(__fadd_rn(us[tid], -s_mx));
    __syncthreads();

    if (w == 0) {
        float sv = __fadd_rn(__fadd_rn(es[lane], es[lane + 32]),
                             __fadd_rn(es[lane + 64], es[lane + 96]));
#pragma unroll
        for (int o = 16; o; o >>= 1)
            sv = __fadd_rn(sv, __shfl_xor_sync(0xffffffffu, sv, o));
        if (lane == 0) s_sum = sv;
    }
    __syncthreads();

    {
        float p = __fdiv_rn(es[tid], s_sum);
        ps[tid] = p;
        out_probs[((size_t)step * BSZ + b) * SSZ + tid] = p;
    }
    __syncthreads();

    if (w == 0) {
        float bv = -1.0f;
        int bi = 0;
#pragma unroll
        for (int k = 0; k < 4; k++) {
            int s = lane + 32 * k;
            float v = ps[s];
            if (v > bv) { bv = v; bi = s; }
        }
#pragma unroll
        for (int o = 16; o; o >>= 1) {
            float ov = __shfl_xor_sync(0xffffffffu, bv, o);
            int oi = __shfl_xor_sync(0xffffffffu, bi, o);
            if (ov > bv || (ov == bv && oi < bi)) { bv = ov; bi = oi; }
        }
        if (lane == 0) s_idx = bi;
    }
    __syncthreads();

    int bi = s_idx;
    if (tid == 0) {
        g_mask[b * SSZ + bi] = 0;
        if (out_idx) out_idx[(size_t)b * SSZ + step] = (float)bi;
    }

    if (h_out) {
        const float* Cb = g_C + (size_t)b * GSZ;
        const float* xr = g_xg_dec + ((size_t)b * SSZ + bi) * GSZ;
#pragma unroll
        for (int j = 0; j < 4; j++) {
            int hh = tid + 128 * j;
            int n4 = 4 * hh;
            int idx = b * HSZ + hh;
            float gi = __fadd_rn(xr[n4 + 0], Cb[n4 + 0]);
            float gf = __fadd_rn(xr[n4 + 1], Cb[n4 + 1]);
            float gg = __fadd_rn(xr[n4 + 2], Cb[n4 + 2]);
            float go = __fadd_rn(xr[n4 + 3], Cb[n4 + 3]);
            float si = sigf(gi), sf = sigf(gf), so = sigf(go);
            float tg = xtanh(gg);
            float cn = __fadd_rn(__fmul_rn(sf, g_c[idx]), __fmul_rn(si, tg));
            g_c[idx] = cn;
            h_out[idx] = __fmul_rn(so, xtanh(cn));
        }
    }
}

// ---------- host ----------
extern "C" void kernel_launch(void* const* d_in, const int* in_sizes, int n_in,
                              void* d_out, int out_size) {
    const float* inputs  = (const float*)d_in[0];
    const float* emb_W   = (const float*)d_in[2];
    const float* emb_b   = (const float*)d_in[3];
    const float* enc_Wih = (const float*)d_in[4];
    const float* enc_Whh = (const float*)d_in[5];
    const float* enc_bih = (const float*)d_in[6];
    const float* enc_bhh = (const float*)d_in[7];
    const float* h0      = (const float*)d_in[8];
    const float* c0      = (const float*)d_in[9];
    const float* dec0    = (const float*)d_in[10];
    const float* dec_Wih = (const float*)d_in[11];
    const float* dec_Whh = (const float*)d_in[12];
    const float* dec_bih = (const float*)d_in[13];
    const float* dec_bhh = (const float*)d_in[14];
    const float* W1      = (const float*)d_in[15];
    const float* b1      = (const float*)d_in[16];
    const float* W2      = (const float*)d_in[17];
    const float* b2      = (const float*)d_in[18];
    const float* V       = (const float*)d_in[19];

    float *phall, *phdec, *pWencG, *pWdecT, *pxg_enc, *pxg0;
    cudaGetSymbolAddress((void**)&phall,   g_hall);
    cudaGetSymbolAddress((void**)&phdec,   g_hdec);
    cudaGetSymbolAddress((void**)&pWencG,  g_WencG);
    cudaGetSymbolAddress((void**)&pWdecT,  g_WdecT);
    cudaGetSymbolAddress((void**)&pxg_enc, g_xg_enc);
    cudaGetSymbolAddress((void**)&pxg0,    g_xg0);

    float* out_probs = (float*)d_out;
    const size_t PROBS_N = (size_t)SSZ * BSZ * SSZ;
    float* out_idx = ((size_t)out_size >= PROBS_N + (size_t)BSZ * SSZ)
                         ? out_probs + PROBS_N : nullptr;

    dim3 ge(GSZ / 64, BSZ / 64);        // 32 x 4 = 128 blocks (gates gemm)
    dim3 gq(HSZ / 64, BSZ / 64);        // 8 x 4 = 32 blocks (q gemm)
    dim3 gp(HSZ / 64, BSZ * SSZ / 64);  // proj
    dim3 gx(NB2 / 64, BSZ * SSZ / 64);  // xg
    dim3 ga(BSZ, 8);                    // attn_u

    const size_t HB = (size_t)BSZ * HSZ;
    const size_t XB = (size_t)SSZ * GSZ;

    init_kernel<<<(BSZ * HSZ + 255) / 256, 256>>>(h0, c0, inputs);
    transpose_kernel<<<(HSZ * NC + 255) / 256, 256>>>(enc_Whh, W1, dec_Whh, W2);
    emb_kernel<<<(BSZ * SSZ * ESZ + 255) / 256, 256>>>(inputs, emb_W, emb_b);
    gemm_step<<<ge, 256>>>(phall, pWencG, GSZ, 0, nullptr, 0, nullptr);   // profiled slot
    wiht_kernel<<<(ESZ * NB2 + 255) / 256, 256>>>(enc_Wih, dec_Wih);
    xg_gemm<<<gx, 256>>>(enc_bih, enc_bhh, dec_bih, dec_bhh);
    xg0_kernel<<<GSZ / 256, 256>>>(dec_Wih, dec_bih, dec_bhh, dec0);
    cell0_kernel<<<BSZ * HSZ / 256, 256>>>(phall + HB, pxg_enc);

    for (int t = 1; t < SSZ; t++)
        gemm_step<<<ge, 256>>>(phall + (size_t)t * HB, pWencG, GSZ, 1,
                               pxg_enc + (size_t)t * GSZ, XB,
                               phall + (size_t)(t + 1) * HB);

    proj_gemm<<<gp, 256>>>(b1);

    // PDL launch config for attn_u (overlaps with the preceding gates gemm,
    // which triggers completion at kernel start; attn_u reads nothing it writes).
    cudaLaunchConfig_t cfg = {};
    cfg.gridDim = ga;
    cfg.blockDim = dim3(256, 1, 1);
    cfg.dynamicSmemBytes = 0;
    cfg.stream = 0;
    cudaLaunchAttribute attrs[1];
    attrs[0].id = cudaLaunchAttributeProgrammaticStreamSerialization;
    attrs[0].val.programmaticStreamSerializationAllowed = 1;
    cfg.attrs = attrs;
    cfg.numAttrs = 1;

    float* hb[2] = {phall + (size_t)SSZ * HB, phdec};
    int cur = 0;
    for (int t = 0; t < SSZ; t++) {
        if (t == 0) {
            gemm_step<<<ge, 256>>>(hb[cur], pWdecT, NC, 1, pxg0, 0, hb[cur ^ 1]);
        } else {
            q_gemm<<<gq, 256>>>(hb[cur], b2);
            gemm_step<<<ge, 256>>>(hb[cur], pWdecT, NC, 0, nullptr, 0, nullptr);
            cudaLaunchKernelEx(&cfg, attn_u_kernel, V);
            attn_fin_kernel<<<BSZ, 128>>>(t - 1, out_probs, out_idx, hb[cur ^ 1]);
        }
        cur ^= 1;
    }
    q_gemm<<<gq, 256>>>(hb[cur], b2);
    attn_u_kernel<<<ga, 256>>>(V);
    attn_fin_kernel<<<BSZ, 128>>>(SSZ - 1, out_probs, out_idx, nullptr);
}